// round 2
// baseline (speedup 1.0000x reference)
#include <cuda_runtime.h>
#include <math.h>

#define T_TOK 4096
#define H_DIM 1024
#define N_EXP 8
#define F_DIM 4096
#define TOPK  2
#define SLOTS (T_TOK*TOPK)

// ---- static device scratch (allocation-free contract) ----
__device__ int   g_count[N_EXP];
__device__ int   g_cursor[N_EXP];
__device__ int   g_off[N_EXP + 1];
__device__ int   g_top_e[T_TOK * TOPK];
__device__ float g_top_w[T_TOK * TOPK];
__device__ int   g_tok[SLOTS];
__device__ float g_wgt[SLOTS];
__device__ float g_h[(size_t)SLOTS * F_DIM];   // 128 MB hidden activations

__global__ void zero_kernel() {
    int i = threadIdx.x;
    if (i < N_EXP) { g_count[i] = 0; g_cursor[i] = 0; }
}

__global__ void router_kernel(const float* __restrict__ x,
                              const float* __restrict__ rw) {
    int t    = blockIdx.x;
    int warp = threadIdx.x >> 5;
    int lane = threadIdx.x & 31;
    const float* xt = x  + (size_t)t * H_DIM;
    const float* we = rw + (size_t)warp * H_DIM;
    float s = 0.f;
    for (int i = lane; i < H_DIM; i += 32) s = fmaf(xt[i], we[i], s);
    #pragma unroll
    for (int o = 16; o; o >>= 1) s += __shfl_xor_sync(0xffffffffu, s, o);
    __shared__ float logits[N_EXP];
    if (lane == 0) logits[warp] = s;
    __syncthreads();
    if (threadIdx.x == 0) {
        float m = logits[0];
        #pragma unroll
        for (int e = 1; e < N_EXP; e++) m = fmaxf(m, logits[e]);
        float p[N_EXP]; float den = 0.f;
        #pragma unroll
        for (int e = 0; e < N_EXP; e++) { p[e] = expf(logits[e] - m); den += p[e]; }
        float inv = 1.f / den;
        #pragma unroll
        for (int e = 0; e < N_EXP; e++) p[e] *= inv;
        // top-2, lower index wins ties (matches jax.lax.top_k)
        int e1 = 0;
        #pragma unroll
        for (int e = 1; e < N_EXP; e++) if (p[e] > p[e1]) e1 = e;
        int e2 = (e1 == 0) ? 1 : 0;
        #pragma unroll
        for (int e = 0; e < N_EXP; e++) if (e != e1 && p[e] > p[e2]) e2 = e;
        g_top_e[2*t]     = e1; g_top_w[2*t]     = p[e1];
        g_top_e[2*t + 1] = e2; g_top_w[2*t + 1] = p[e2];
        atomicAdd(&g_count[e1], 1);
        atomicAdd(&g_count[e2], 1);
    }
}

__global__ void offsets_kernel() {
    if (threadIdx.x == 0) {
        int acc = 0;
        for (int e = 0; e < N_EXP; e++) { g_off[e] = acc; acc += g_count[e]; }
        g_off[N_EXP] = acc;
    }
}

__global__ void fill_kernel() {
    int t = blockIdx.x * blockDim.x + threadIdx.x;
    if (t >= T_TOK) return;
    #pragma unroll
    for (int k = 0; k < TOPK; k++) {
        int e   = g_top_e[2*t + k];
        int pos = atomicAdd(&g_cursor[e], 1);
        int s   = g_off[e] + pos;
        g_tok[s] = t;
        g_wgt[s] = g_top_w[2*t + k];
    }
}

__device__ __forceinline__ float gelu_tanh(float v) {
    const float c = 0.7978845608028654f;          // sqrt(2/pi)
    float u = c * (v + 0.044715f * v * v * v);
    return 0.5f * v * (1.f + tanhf(u));
}

// ---- GEMM1: h = gelu(x @ w1[e]^T) * (x @ v1[e]^T), gathered rows ----
// BM=64, BN=64, BK=16, 256 threads, 4x4 microtile
__global__ void __launch_bounds__(256) gemm1_kernel(
        const float* __restrict__ x,
        const float* __restrict__ w1,
        const float* __restrict__ v1) {
    int e   = blockIdx.z;
    int n0  = g_off[e];
    int cnt = g_off[e + 1] - n0;
    int r0  = blockIdx.y * 64;
    if (r0 >= cnt) return;
    int f0  = blockIdx.x * 64;

    __shared__ float As [16][64];
    __shared__ float B1s[16][64];
    __shared__ float B2s[16][64];
    __shared__ int   toks[64];

    int tid = threadIdx.x;
    if (tid < 64) toks[tid] = (r0 + tid < cnt) ? g_tok[n0 + r0 + tid] : -1;
    __syncthreads();

    int lr = tid >> 2, lk4 = tid & 3;       // loader: row 0..63, float4 index along K
    int tx = tid & 15, ty = tid >> 4;       // compute: 16x16 grid, 4x4 each

    const float* W1 = w1 + (size_t)e * F_DIM * H_DIM + (size_t)(f0 + lr) * H_DIM + lk4 * 4;
    const float* V1 = v1 + (size_t)e * F_DIM * H_DIM + (size_t)(f0 + lr) * H_DIM + lk4 * 4;
    int tok = toks[lr];
    const float* A = (tok >= 0) ? (x + (size_t)tok * H_DIM + lk4 * 4) : nullptr;

    float acc1[4][4], acc2[4][4];
    #pragma unroll
    for (int i = 0; i < 4; i++)
        #pragma unroll
        for (int j = 0; j < 4; j++) { acc1[i][j] = 0.f; acc2[i][j] = 0.f; }

    for (int k0 = 0; k0 < H_DIM; k0 += 16) {
        float4 av = A ? *(const float4*)(A + k0) : make_float4(0.f, 0.f, 0.f, 0.f);
        float4 b1 = *(const float4*)(W1 + k0);
        float4 b2 = *(const float4*)(V1 + k0);
        __syncthreads();
        As [lk4*4+0][lr] = av.x; As [lk4*4+1][lr] = av.y; As [lk4*4+2][lr] = av.z; As [lk4*4+3][lr] = av.w;
        B1s[lk4*4+0][lr] = b1.x; B1s[lk4*4+1][lr] = b1.y; B1s[lk4*4+2][lr] = b1.z; B1s[lk4*4+3][lr] = b1.w;
        B2s[lk4*4+0][lr] = b2.x; B2s[lk4*4+1][lr] = b2.y; B2s[lk4*4+2][lr] = b2.z; B2s[lk4*4+3][lr] = b2.w;
        __syncthreads();
        #pragma unroll
        for (int k = 0; k < 16; k++) {
            float4 a = *(const float4*)&As [k][ty * 4];
            float4 p = *(const float4*)&B1s[k][tx * 4];
            float4 q = *(const float4*)&B2s[k][tx * 4];
            float aa[4] = {a.x, a.y, a.z, a.w};
            float pp[4] = {p.x, p.y, p.z, p.w};
            float qq[4] = {q.x, q.y, q.z, q.w};
            #pragma unroll
            for (int i = 0; i < 4; i++)
                #pragma unroll
                for (int j = 0; j < 4; j++) {
                    acc1[i][j] = fmaf(aa[i], pp[j], acc1[i][j]);
                    acc2[i][j] = fmaf(aa[i], qq[j], acc2[i][j]);
                }
        }
    }

    #pragma unroll
    for (int i = 0; i < 4; i++) {
        int r = ty * 4 + i;
        if (r0 + r < cnt) {
            float4 o;
            o.x = gelu_tanh(acc1[i][0]) * acc2[i][0];
            o.y = gelu_tanh(acc1[i][1]) * acc2[i][1];
            o.z = gelu_tanh(acc1[i][2]) * acc2[i][2];
            o.w = gelu_tanh(acc1[i][3]) * acc2[i][3];
            *(float4*)&g_h[(size_t)(n0 + r0 + r) * F_DIM + f0 + tx * 4] = o;
        }
    }
}

// ---- GEMM2: out[tok] += wgt * (h @ w2[e]),  w2[e] is [F,H] K-major-in-rows ----
__global__ void __launch_bounds__(256) gemm2_kernel(
        const float* __restrict__ w2, float* __restrict__ out) {
    int e   = blockIdx.z;
    int n0  = g_off[e];
    int cnt = g_off[e + 1] - n0;
    int r0  = blockIdx.y * 64;
    if (r0 >= cnt) return;
    int h0  = blockIdx.x * 64;

    __shared__ float As[16][64];
    __shared__ float Bs[16][64];
    __shared__ int   toks[64];
    __shared__ float wgts[64];

    int tid = threadIdx.x;
    if (tid < 64) {
        bool v = (r0 + tid) < cnt;
        toks[tid] = v ? g_tok[n0 + r0 + tid] : -1;
        wgts[tid] = v ? g_wgt[n0 + r0 + tid] : 0.f;
    }
    __syncthreads();

    int lr = tid >> 2, lk4 = tid & 3;   // A loader
    int bk = tid >> 4, bn4 = tid & 15;  // B loader: k row 0..15, float4 along n
    int tx = tid & 15, ty = tid >> 4;

    bool arow = (r0 + lr) < cnt;
    int  slot = arow ? (n0 + r0 + lr) : 0;
    const float* A = g_h + (size_t)slot * F_DIM + lk4 * 4;
    const float* B = w2 + (size_t)e * F_DIM * H_DIM + (size_t)bk * H_DIM + h0 + bn4 * 4;

    float acc[4][4];
    #pragma unroll
    for (int i = 0; i < 4; i++)
        #pragma unroll
        for (int j = 0; j < 4; j++) acc[i][j] = 0.f;

    for (int k0 = 0; k0 < F_DIM; k0 += 16) {
        float4 av = arow ? *(const float4*)(A + k0) : make_float4(0.f, 0.f, 0.f, 0.f);
        float4 bv = *(const float4*)(B + (size_t)k0 * H_DIM);
        __syncthreads();
        As[lk4*4+0][lr] = av.x; As[lk4*4+1][lr] = av.y; As[lk4*4+2][lr] = av.z; As[lk4*4+3][lr] = av.w;
        *(float4*)&Bs[bk][bn4 * 4] = bv;
        __syncthreads();
        #pragma unroll
        for (int k = 0; k < 16; k++) {
            float4 a = *(const float4*)&As[k][ty * 4];
            float4 b = *(const float4*)&Bs[k][tx * 4];
            float aa[4] = {a.x, a.y, a.z, a.w};
            float bb[4] = {b.x, b.y, b.z, b.w};
            #pragma unroll
            for (int i = 0; i < 4; i++)
                #pragma unroll
                for (int j = 0; j < 4; j++)
                    acc[i][j] = fmaf(aa[i], bb[j], acc[i][j]);
        }
    }

    #pragma unroll
    for (int i = 0; i < 4; i++) {
        int r = ty * 4 + i;
        if (r0 + r < cnt) {
            int   tok = toks[r];
            float w   = wgts[r];
            float* op = out + (size_t)tok * H_DIM + h0 + tx * 4;
            atomicAdd(op + 0, w * acc[i][0]);
            atomicAdd(op + 1, w * acc[i][1]);
            atomicAdd(op + 2, w * acc[i][2]);
            atomicAdd(op + 3, w * acc[i][3]);
        }
    }
}

extern "C" void kernel_launch(void* const* d_in, const int* in_sizes, int n_in,
                              void* d_out, int out_size) {
    const float* x  = (const float*)d_in[0];
    const float* rw = (const float*)d_in[1];
    const float* w1 = (const float*)d_in[2];
    const float* v1 = (const float*)d_in[3];
    const float* w2 = (const float*)d_in[4];
    float* out = (float*)d_out;

    cudaMemsetAsync(d_out, 0, (size_t)out_size * sizeof(float), 0);
    zero_kernel<<<1, 32>>>();
    router_kernel<<<T_TOK, 256>>>(x, rw);
    offsets_kernel<<<1, 1>>>();
    fill_kernel<<<T_TOK / 256, 256>>>();
    gemm1_kernel<<<dim3(F_DIM / 64, T_TOK / 64, N_EXP), 256>>>(x, w1, v1);
    gemm2_kernel<<<dim3(H_DIM / 64, T_TOK / 64, N_EXP), 256>>>(w2, out);
}

// round 13
// speedup vs baseline: 2.1834x; 2.1834x over previous
#include <cuda_runtime.h>
#include <math.h>
#include <stdint.h>

#define T_TOK 4096
#define H_DIM 1024
#define N_EXP 8
#define F_DIM 4096
#define TOPK  2
#define SLOTS (T_TOK*TOPK)

__device__ int   g_count[N_EXP];
__device__ int   g_cursor[N_EXP];
__device__ int   g_off[N_EXP + 1];
__device__ int   g_top_e[T_TOK * TOPK];
__device__ float g_top_w[T_TOK * TOPK];
__device__ int   g_tok[SLOTS];
__device__ float g_wgt[SLOTS];
__device__ float g_h[(size_t)SLOTS * F_DIM];
__device__ float g_w2t[(size_t)N_EXP * H_DIM * F_DIM];

__device__ __forceinline__ float to_tf32(float x) {
    uint32_t r; asm("cvt.rna.tf32.f32 %0, %1;" : "=r"(r) : "f"(x));
    return __uint_as_float(r);
}

// D += A(16x8,row) * B(8x8,col)   tf32 inputs, f32 accum
#define MMA_TF32(d, a, b0, b1) \
    asm volatile("mma.sync.aligned.m16n8k8.row.col.f32.tf32.tf32.f32 " \
        "{%0,%1,%2,%3}, {%4,%5,%6,%7}, {%8,%9}, {%0,%1,%2,%3};" \
        : "+f"((d)[0]), "+f"((d)[1]), "+f"((d)[2]), "+f"((d)[3]) \
        : "r"((a)[0]), "r"((a)[1]), "r"((a)[2]), "r"((a)[3]), "r"(b0), "r"(b1))

__device__ __forceinline__ void sts_cvt(float* p, float4 v) {
    p[0] = to_tf32(v.x); p[1] = to_tf32(v.y); p[2] = to_tf32(v.z); p[3] = to_tf32(v.w);
}
__device__ __forceinline__ void sts_raw(float* p, float4 v) {
    p[0] = v.x; p[1] = v.y; p[2] = v.z; p[3] = v.w;
}

__global__ void zero_kernel() {
    int i = threadIdx.x;
    if (i < N_EXP) { g_count[i] = 0; g_cursor[i] = 0; }
}

__global__ void router_kernel(const float* __restrict__ x,
                              const float* __restrict__ rw) {
    int t    = blockIdx.x;
    int warp = threadIdx.x >> 5;
    int lane = threadIdx.x & 31;
    const float* xt = x  + (size_t)t * H_DIM;
    const float* we = rw + (size_t)warp * H_DIM;
    float s = 0.f;
    for (int i = lane; i < H_DIM; i += 32) s = fmaf(xt[i], we[i], s);
    #pragma unroll
    for (int o = 16; o; o >>= 1) s += __shfl_xor_sync(0xffffffffu, s, o);
    __shared__ float logits[N_EXP];
    if (lane == 0) logits[warp] = s;
    __syncthreads();
    if (threadIdx.x == 0) {
        float m = logits[0];
        #pragma unroll
        for (int e = 1; e < N_EXP; e++) m = fmaxf(m, logits[e]);
        float p[N_EXP]; float den = 0.f;
        #pragma unroll
        for (int e = 0; e < N_EXP; e++) { p[e] = expf(logits[e] - m); den += p[e]; }
        float inv = 1.f / den;
        #pragma unroll
        for (int e = 0; e < N_EXP; e++) p[e] *= inv;
        int e1 = 0;
        #pragma unroll
        for (int e = 1; e < N_EXP; e++) if (p[e] > p[e1]) e1 = e;
        int e2 = (e1 == 0) ? 1 : 0;
        #pragma unroll
        for (int e = 0; e < N_EXP; e++) if (e != e1 && p[e] > p[e2]) e2 = e;
        g_top_e[2*t]     = e1; g_top_w[2*t]     = p[e1];
        g_top_e[2*t + 1] = e2; g_top_w[2*t + 1] = p[e2];
        atomicAdd(&g_count[e1], 1);
        atomicAdd(&g_count[e2], 1);
    }
}

__global__ void offsets_kernel() {
    if (threadIdx.x == 0) {
        int acc = 0;
        for (int e = 0; e < N_EXP; e++) { g_off[e] = acc; acc += g_count[e]; }
        g_off[N_EXP] = acc;
    }
}

__global__ void fill_kernel() {
    int t = blockIdx.x * blockDim.x + threadIdx.x;
    if (t >= T_TOK) return;
    #pragma unroll
    for (int k = 0; k < TOPK; k++) {
        int e   = g_top_e[2*t + k];
        int pos = atomicAdd(&g_cursor[e], 1);
        int s   = g_off[e] + pos;
        g_tok[s] = t;
        g_wgt[s] = g_top_w[2*t + k];
    }
}

// g_w2t[e][h][f] = tf32(w2[e][f][h])
__global__ void __launch_bounds__(256) w2t_kernel(const float* __restrict__ w2) {
    int e  = blockIdx.z;
    int h0 = blockIdx.x * 32;
    int f0 = blockIdx.y * 32;
    __shared__ float tile[32][33];
    int tx = threadIdx.x & 31, ty = threadIdx.x >> 5;
    const float* src = w2 + ((size_t)e * F_DIM + f0) * H_DIM + h0;
    #pragma unroll
    for (int j = 0; j < 32; j += 8)
        tile[ty + j][tx] = src[(size_t)(ty + j) * H_DIM + tx];
    __syncthreads();
    float* dst = g_w2t + ((size_t)e * H_DIM + h0) * F_DIM + f0;
    #pragma unroll
    for (int j = 0; j < 32; j += 8)
        dst[(size_t)(ty + j) * F_DIM + tx] = to_tf32(tile[tx][ty + j]);
}

__device__ __forceinline__ float gelu_tanh(float v) {
    const float c = 0.7978845608028654f;
    float u = c * (v + 0.044715f * v * v * v);
    return 0.5f * v * (1.f + tanhf(u));
}

// ---- GEMM1: tile 128x64, BK=16, dual accumulators (w1, v1) ----
#define LDP 17
#define NC1 (H_DIM / 16)
#define G1_AS    0
#define G1_B1S   (2 * 128 * LDP)
#define G1_B2S   (G1_B1S + 2 * 64 * LDP)
#define G1_TOKS  (G1_B2S + 2 * 64 * LDP)
#define G1_SMEM  ((G1_TOKS + 128) * 4)

__global__ void __launch_bounds__(256) gemm1_mma(
        const float* __restrict__ x,
        const float* __restrict__ w1,
        const float* __restrict__ v1) {
    int e   = blockIdx.z;
    int n0  = g_off[e];
    int cnt = g_off[e + 1] - n0;
    int r0  = blockIdx.x * 128;
    if (r0 >= cnt) return;
    int f0  = blockIdx.y * 64;

    extern __shared__ float sm1[];
    float* As  = sm1 + G1_AS;
    float* B1s = sm1 + G1_B1S;
    float* B2s = sm1 + G1_B2S;
    int*   toks = (int*)(sm1 + G1_TOKS);

    int tid = threadIdx.x;
    if (tid < 128) toks[tid] = (r0 + tid < cnt) ? g_tok[n0 + r0 + tid] : 0;
    __syncthreads();

    int lane = tid & 31, wid = tid >> 5;
    int gid = lane >> 2, tig = lane & 3;
    int wm = (wid & 3) * 32, wn = (wid >> 2) * 32;

    const float* ap[2]; int aoff[2];
    #pragma unroll
    for (int i = 0; i < 2; i++) {
        int idx = tid + 256 * i;
        int row = idx >> 2, c4 = idx & 3;
        ap[i]   = x + (size_t)toks[row] * H_DIM + c4 * 4;
        aoff[i] = row * LDP + c4 * 4;
    }
    int brow = tid >> 2, bc4 = tid & 3;
    const float* b1p = w1 + ((size_t)e * F_DIM + f0 + brow) * H_DIM + bc4 * 4;
    const float* b2p = v1 + ((size_t)e * F_DIM + f0 + brow) * H_DIM + bc4 * 4;
    int boff = brow * LDP + bc4 * 4;

    float acc1[2][4][4], acc2[2][4][4];
    #pragma unroll
    for (int i = 0; i < 2; i++)
        #pragma unroll
        for (int j = 0; j < 4; j++)
            #pragma unroll
            for (int k = 0; k < 4; k++) { acc1[i][j][k] = 0.f; acc2[i][j][k] = 0.f; }

    float4 rA0 = *(const float4*)ap[0];
    float4 rA1 = *(const float4*)ap[1];
    float4 rB1 = *(const float4*)b1p;
    float4 rB2 = *(const float4*)b2p;
    sts_cvt(&As[aoff[0]], rA0);
    sts_cvt(&As[aoff[1]], rA1);
    sts_cvt(&B1s[boff], rB1);
    sts_cvt(&B2s[boff], rB2);
    __syncthreads();

    for (int c = 0; c < NC1; c++) {
        int sA = (c & 1) * 128 * LDP;
        int sB = (c & 1) * 64 * LDP;
        if (c + 1 < NC1) {
            int k0 = (c + 1) * 16;
            rA0 = *(const float4*)(ap[0] + k0);
            rA1 = *(const float4*)(ap[1] + k0);
            rB1 = *(const float4*)(b1p + k0);
            rB2 = *(const float4*)(b2p + k0);
        }
        #pragma unroll
        for (int ks = 0; ks < 16; ks += 8) {
            uint32_t a[2][4];
            #pragma unroll
            for (int ma = 0; ma < 2; ma++) {
                int rb = sA + (wm + ma * 16 + gid) * LDP + ks + tig;
                a[ma][0] = __float_as_uint(As[rb]);
                a[ma][1] = __float_as_uint(As[rb + 8 * LDP]);
                a[ma][2] = __float_as_uint(As[rb + 4]);
                a[ma][3] = __float_as_uint(As[rb + 8 * LDP + 4]);
            }
            #pragma unroll
            for (int nb = 0; nb < 4; nb++) {
                int nbase = sB + (wn + nb * 8 + gid) * LDP + ks + tig;
                uint32_t p0 = __float_as_uint(B1s[nbase]);
                uint32_t p1 = __float_as_uint(B1s[nbase + 4]);
                uint32_t q0 = __float_as_uint(B2s[nbase]);
                uint32_t q1 = __float_as_uint(B2s[nbase + 4]);
                #pragma unroll
                for (int ma = 0; ma < 2; ma++) {
                    MMA_TF32(acc1[ma][nb], a[ma], p0, p1);
                    MMA_TF32(acc2[ma][nb], a[ma], q0, q1);
                }
            }
        }
        if (c + 1 < NC1) {
            int nA = ((c + 1) & 1) * 128 * LDP;
            int nB = ((c + 1) & 1) * 64 * LDP;
            sts_cvt(&As[nA + aoff[0]], rA0);
            sts_cvt(&As[nA + aoff[1]], rA1);
            sts_cvt(&B1s[nB + boff], rB1);
            sts_cvt(&B2s[nB + boff], rB2);
            __syncthreads();
        }
    }

    // epilogue: gelu(acc1)*acc2 -> g_h
    #pragma unroll
    for (int ma = 0; ma < 2; ma++) {
        #pragma unroll
        for (int nb = 0; nb < 4; nb++) {
            int row0 = wm + ma * 16 + gid;
            int col  = f0 + wn + nb * 8 + 2 * tig;
            if (r0 + row0 < cnt) {
                float2 v;
                v.x = to_tf32(gelu_tanh(acc1[ma][nb][0]) * acc2[ma][nb][0]);
                v.y = to_tf32(gelu_tanh(acc1[ma][nb][1]) * acc2[ma][nb][1]);
                *(float2*)&g_h[(size_t)(n0 + r0 + row0) * F_DIM + col] = v;
            }
            if (r0 + row0 + 8 < cnt) {
                float2 v;
                v.x = to_tf32(gelu_tanh(acc1[ma][nb][2]) * acc2[ma][nb][2]);
                v.y = to_tf32(gelu_tanh(acc1[ma][nb][3]) * acc2[ma][nb][3]);
                *(float2*)&g_h[(size_t)(n0 + r0 + row0 + 8) * F_DIM + col] = v;
            }
        }
    }
}

// ---- GEMM2: tile 128x64 over K=F_DIM, out[tok] += wgt * (g_h @ g_w2t^T) ----
#define NC2 (F_DIM / 16)
#define G2_AS    0
#define G2_BS    (2 * 128 * LDP)
#define G2_TOKS  (G2_BS + 2 * 64 * LDP)
#define G2_WGTS  (G2_TOKS + 128)
#define G2_SMEM  ((G2_WGTS + 128) * 4)

__global__ void __launch_bounds__(256) gemm2_mma(float* __restrict__ out) {
    int e   = blockIdx.z;
    int n0  = g_off[e];
    int cnt = g_off[e + 1] - n0;
    int r0  = blockIdx.y * 128;
    if (r0 >= cnt) return;
    int h0  = blockIdx.x * 64;

    extern __shared__ float sm2[];
    float* As   = sm2 + G2_AS;
    float* Bs   = sm2 + G2_BS;
    int*   toks = (int*)(sm2 + G2_TOKS);
    float* wgts = sm2 + G2_WGTS;

    int tid = threadIdx.x;
    if (tid < 128) {
        bool v = (r0 + tid) < cnt;
        toks[tid] = v ? g_tok[n0 + r0 + tid] : 0;
        wgts[tid] = v ? g_wgt[n0 + r0 + tid] : 0.f;
    }
    __syncthreads();

    int lane = tid & 31, wid = tid >> 5;
    int gid = lane >> 2, tig = lane & 3;
    int wm = (wid & 3) * 32, wn = (wid >> 2) * 32;

    const float* ap[2]; int aoff[2];
    #pragma unroll
    for (int i = 0; i < 2; i++) {
        int idx = tid + 256 * i;
        int row = idx >> 2, c4 = idx & 3;
        int rr  = (r0 + row < cnt) ? (r0 + row) : (cnt - 1);
        ap[i]   = g_h + (size_t)(n0 + rr) * F_DIM + c4 * 4;
        aoff[i] = row * LDP + c4 * 4;
    }
    int brow = tid >> 2, bc4 = tid & 3;
    const float* bp = g_w2t + ((size_t)e * H_DIM + h0 + brow) * F_DIM + bc4 * 4;
    int boff = brow * LDP + bc4 * 4;

    float acc[2][4][4];
    #pragma unroll
    for (int i = 0; i < 2; i++)
        #pragma unroll
        for (int j = 0; j < 4; j++)
            #pragma unroll
            for (int k = 0; k < 4; k++) acc[i][j][k] = 0.f;

    float4 rA0 = *(const float4*)ap[0];
    float4 rA1 = *(const float4*)ap[1];
    float4 rB  = *(const float4*)bp;
    sts_raw(&As[aoff[0]], rA0);
    sts_raw(&As[aoff[1]], rA1);
    sts_raw(&Bs[boff], rB);
    __syncthreads();

    for (int c = 0; c < NC2; c++) {
        int sA = (c & 1) * 128 * LDP;
        int sB = (c & 1) * 64 * LDP;
        if (c + 1 < NC2) {
            int k0 = (c + 1) * 16;
            rA0 = *(const float4*)(ap[0] + k0);
            rA1 = *(const float4*)(ap[1] + k0);
            rB  = *(const float4*)(bp + k0);
        }
        #pragma unroll
        for (int ks = 0; ks < 16; ks += 8) {
            uint32_t a[2][4];
            #pragma unroll
            for (int ma = 0; ma < 2; ma++) {
                int rb = sA + (wm + ma * 16 + gid) * LDP + ks + tig;
                a[ma][0] = __float_as_uint(As[rb]);
                a[ma][1] = __float_as_uint(As[rb + 8 * LDP]);
                a[ma][2] = __float_as_uint(As[rb + 4]);
                a[ma][3] = __float_as_uint(As[rb + 8 * LDP + 4]);
            }
            #pragma unroll
            for (int nb = 0; nb < 4; nb++) {
                int nbase = sB + (wn + nb * 8 + gid) * LDP + ks + tig;
                uint32_t p0 = __float_as_uint(Bs[nbase]);
                uint32_t p1 = __float_as_uint(Bs[nbase + 4]);
                #pragma unroll
                for (int ma = 0; ma < 2; ma++)
                    MMA_TF32(acc[ma][nb], a[ma], p0, p1);
            }
        }
        if (c + 1 < NC2) {
            int nA = ((c + 1) & 1) * 128 * LDP;
            int nB = ((c + 1) & 1) * 64 * LDP;
            sts_raw(&As[nA + aoff[0]], rA0);
            sts_raw(&As[nA + aoff[1]], rA1);
            sts_raw(&Bs[nB + boff], rB);
            __syncthreads();
        }
    }

    #pragma unroll
    for (int ma = 0; ma < 2; ma++) {
        #pragma unroll
        for (int nb = 0; nb < 4; nb++) {
            int row0 = wm + ma * 16 + gid;
            int col  = h0 + wn + nb * 8 + 2 * tig;
            if (r0 + row0 < cnt) {
                float w = wgts[row0];
                float* op = out + (size_t)toks[row0] * H_DIM + col;
                atomicAdd(op,     w * acc[ma][nb][0]);
                atomicAdd(op + 1, w * acc[ma][nb][1]);
            }
            if (r0 + row0 + 8 < cnt) {
                float w = wgts[row0 + 8];
                float* op = out + (size_t)toks[row0 + 8] * H_DIM + col;
                atomicAdd(op,     w * acc[ma][nb][2]);
                atomicAdd(op + 1, w * acc[ma][nb][3]);
            }
        }
    }
}

extern "C" void kernel_launch(void* const* d_in, const int* in_sizes, int n_in,
                              void* d_out, int out_size) {
    const float* x  = (const float*)d_in[0];
    const float* rw = (const float*)d_in[1];
    const float* w1 = (const float*)d_in[2];
    const float* v1 = (const float*)d_in[3];
    const float* w2 = (const float*)d_in[4];
    float* out = (float*)d_out;

    cudaFuncSetAttribute(gemm1_mma, cudaFuncAttributeMaxDynamicSharedMemorySize, G1_SMEM);
    cudaFuncSetAttribute(gemm2_mma, cudaFuncAttributeMaxDynamicSharedMemorySize, G2_SMEM);

    cudaMemsetAsync(d_out, 0, (size_t)out_size * sizeof(float), 0);
    zero_kernel<<<1, 32>>>();
    router_kernel<<<T_TOK, 256>>>(x, rw);
    offsets_kernel<<<1, 1>>>();
    fill_kernel<<<T_TOK / 256, 256>>>();
    w2t_kernel<<<dim3(H_DIM / 32, F_DIM / 32, N_EXP), 256>>>(w2);
    gemm1_mma<<<dim3(SLOTS / 128, F_DIM / 64, N_EXP), 256, G1_SMEM>>>(x, w1, v1);
    gemm2_mma<<<dim3(H_DIM / 64, SLOTS / 128, N_EXP), 256, G2_SMEM>>>(out);
}